// round 1
// baseline (speedup 1.0000x reference)
#include <cuda_runtime.h>
#include <cuda_bf16.h>

// GraphAttentionLayer: out = elu(softmax(h_j @ a_j + const) @ h_j)
// Single-pass online softmax over 200000 rows of 128 floats (102.4 MB, read once).
// h_i . a_i is a constant shift on all logits -> cancels in softmax -> skipped.

#define D        128
#define NB       256          // blocks in pass 1
#define NT       512          // threads per block
#define WPB      (NT / 32)    // 16 warps per block
#define NW       (NB * WPB)   // 4096 warps total

// Scratch: per-block partials (allocation-free rule -> __device__ globals)
__device__ float g_m[NB];
__device__ float g_s[NB];
__device__ float g_acc[NB * D];

__device__ __forceinline__ float dot4(const float4& h, const float4& a) {
    return h.x * a.x + h.y * a.y + h.z * a.z + h.w * a.w;
}

__device__ __forceinline__ void online_update(float d, const float4& h,
                                              float& m, float& s, float4& acc) {
    float mn = fmaxf(m, d);
    float c  = __expf(m - mn);   // rescale old accumulator
    float w  = __expf(d - mn);   // weight of this row
    s     = s * c + w;
    acc.x = acc.x * c + w * h.x;
    acc.y = acc.y * c + w * h.y;
    acc.z = acc.z * c + w * h.z;
    acc.w = acc.w * c + w * h.w;
    m = mn;
}

__global__ __launch_bounds__(NT)
void gat_pass1(const float* __restrict__ hj, const float* __restrict__ a, int nrows) {
    const int warp = threadIdx.x >> 5;
    const int lane = threadIdx.x & 31;

    // a_j slice for this lane's 4 dims (a_j = a[128:256])
    const float4 aj = *reinterpret_cast<const float4*>(a + D + lane * 4);

    const int gw    = blockIdx.x * WPB + warp;
    const int chunk = (nrows + NW - 1) / NW;
    int r0 = gw * chunk;
    int r1 = r0 + chunk;
    if (r0 > nrows) r0 = nrows;
    if (r1 > nrows) r1 = nrows;
    const int n = (r1 > r0) ? (r1 - r0) : 0;

    float  m = -1e30f;          // finite "neg-inf": avoids inf-inf NaN on empty warps
    float  s = 0.0f;
    float4 acc = make_float4(0.f, 0.f, 0.f, 0.f);

    const float* base = hj + (size_t)r0 * D + lane * 4;

    int i = 0;
    // Main loop: 4 rows per iteration -> 4 independent float4 loads in flight
    for (; i + 4 <= n; i += 4) {
        const float* p = base + (size_t)i * D;
        float4 h0 = *reinterpret_cast<const float4*>(p);
        float4 h1 = *reinterpret_cast<const float4*>(p + D);
        float4 h2 = *reinterpret_cast<const float4*>(p + 2 * D);
        float4 h3 = *reinterpret_cast<const float4*>(p + 3 * D);

        float d0 = dot4(h0, aj);
        float d1 = dot4(h1, aj);
        float d2 = dot4(h2, aj);
        float d3 = dot4(h3, aj);

        #pragma unroll
        for (int o = 16; o > 0; o >>= 1) {
            d0 += __shfl_xor_sync(0xffffffffu, d0, o);
            d1 += __shfl_xor_sync(0xffffffffu, d1, o);
            d2 += __shfl_xor_sync(0xffffffffu, d2, o);
            d3 += __shfl_xor_sync(0xffffffffu, d3, o);
        }

        online_update(d0, h0, m, s, acc);
        online_update(d1, h1, m, s, acc);
        online_update(d2, h2, m, s, acc);
        online_update(d3, h3, m, s, acc);
    }
    // Tail
    for (; i < n; ++i) {
        const float* p = base + (size_t)i * D;
        float4 h = *reinterpret_cast<const float4*>(p);
        float d = dot4(h, aj);
        #pragma unroll
        for (int o = 16; o > 0; o >>= 1)
            d += __shfl_xor_sync(0xffffffffu, d, o);
        online_update(d, h, m, s, acc);
    }

    // ---- Block combine in shared memory ----
    __shared__ float sm_m[WPB];
    __shared__ float sm_s[WPB];
    __shared__ __align__(16) float sm_acc[WPB][D];

    if (lane == 0) { sm_m[warp] = m; sm_s[warp] = s; }
    *reinterpret_cast<float4*>(&sm_acc[warp][lane * 4]) = acc;
    __syncthreads();

    if (threadIdx.x < D) {
        const int d = threadIdx.x;
        float M = -1e30f;
        #pragma unroll
        for (int w = 0; w < WPB; ++w) M = fmaxf(M, sm_m[w]);

        float st = 0.f, ad = 0.f;
        #pragma unroll
        for (int w = 0; w < WPB; ++w) {
            float c = __expf(sm_m[w] - M);
            st += sm_s[w] * c;
            ad += sm_acc[w][d] * c;
        }
        g_acc[blockIdx.x * D + d] = ad;
        if (d == 0) { g_m[blockIdx.x] = M; g_s[blockIdx.x] = st; }
    }
}

__global__ __launch_bounds__(D)
void gat_pass2(float* __restrict__ out) {
    const int d = threadIdx.x;  // 0..127

    float M = -1e30f;
    for (int b = 0; b < NB; ++b) M = fmaxf(M, g_m[b]);

    float st = 0.f, ad = 0.f;
    for (int b = 0; b < NB; ++b) {
        float c = __expf(g_m[b] - M);
        st += g_s[b] * c;
        ad += g_acc[b * D + d] * c;   // coalesced across threads
    }

    float h = ad / st;
    out[d] = (h > 0.f) ? h : expm1f(h);   // ELU, alpha = 1
}

extern "C" void kernel_launch(void* const* d_in, const int* in_sizes, int n_in,
                              void* d_out, int out_size) {
    // inputs per metadata: [0] h_i (unused — constant logit shift cancels in softmax),
    //                      [1] h_j [200000,128] f32, [2] a [256,1] f32
    const float* hj = (const float*)d_in[1];
    const float* a  = (const float*)d_in[2];
    const int nrows = in_sizes[1] / D;

    gat_pass1<<<NB, NT>>>(hj, a, nrows);
    gat_pass2<<<1, D>>>((float*)d_out);
}

// round 3
// speedup vs baseline: 1.4287x; 1.4287x over previous
#include <cuda_runtime.h>
#include <cuda_bf16.h>

// GraphAttentionLayer: out = elu(softmax(h_j @ a_j + const) @ h_j)
// Pass 1: single-pass online softmax over 200000x128 f32 (102.4 MB read once).
// h_i . a_i is a constant shift on all logits -> cancels in softmax -> skipped.
// Pass 2: fully parallel combine of 296 block partials in ONE 1024-thread block.

#define D        128
#define NB       296          // blocks in pass 1 (2 * 148 SMs -> perfect 2-wave)
#define NT       512          // threads per block, pass 1
#define WPB      (NT / 32)    // 16 warps per block
#define NW       (NB * WPB)   // warps total
#define NT2      1024         // threads, pass 2
#define GRP      (NT2 / D)    // 8 thread-groups over the dim axis

// Scratch: per-block partials (allocation-free rule -> __device__ globals)
__device__ float g_m[NB];
__device__ float g_s[NB];
__device__ float g_acc[NB * D];

__device__ __forceinline__ float dot4(const float4& h, const float4& a) {
    return h.x * a.x + h.y * a.y + h.z * a.z + h.w * a.w;
}

__device__ __forceinline__ void online_update(float d, const float4& h,
                                              float& m, float& s, float4& acc) {
    float mn = fmaxf(m, d);
    float c  = __expf(m - mn);   // rescale old accumulator
    float w  = __expf(d - mn);   // weight of this row
    s     = s * c + w;
    acc.x = acc.x * c + w * h.x;
    acc.y = acc.y * c + w * h.y;
    acc.z = acc.z * c + w * h.z;
    acc.w = acc.w * c + w * h.w;
    m = mn;
}

__global__ __launch_bounds__(NT)
void gat_pass1(const float* __restrict__ hj, const float* __restrict__ a, int nrows) {
    const int warp = threadIdx.x >> 5;
    const int lane = threadIdx.x & 31;

    // a_j slice for this lane's 4 dims (a_j = a[128:256])
    const float4 aj = *reinterpret_cast<const float4*>(a + D + lane * 4);

    const int gw    = blockIdx.x * WPB + warp;
    const int chunk = (nrows + NW - 1) / NW;
    int r0 = gw * chunk;
    int r1 = r0 + chunk;
    if (r0 > nrows) r0 = nrows;
    if (r1 > nrows) r1 = nrows;
    const int n = (r1 > r0) ? (r1 - r0) : 0;

    float  m = -1e30f;          // finite "neg-inf": no inf-inf NaN on empty warps
    float  s = 0.0f;
    float4 acc = make_float4(0.f, 0.f, 0.f, 0.f);

    const float* base = hj + (size_t)r0 * D + lane * 4;

    int i = 0;
    // 4 rows per iteration -> 4 independent 512B warp loads in flight
    for (; i + 4 <= n; i += 4) {
        const float* p = base + (size_t)i * D;
        float4 h0 = *reinterpret_cast<const float4*>(p);
        float4 h1 = *reinterpret_cast<const float4*>(p + D);
        float4 h2 = *reinterpret_cast<const float4*>(p + 2 * D);
        float4 h3 = *reinterpret_cast<const float4*>(p + 3 * D);

        float d0 = dot4(h0, aj);
        float d1 = dot4(h1, aj);
        float d2 = dot4(h2, aj);
        float d3 = dot4(h3, aj);

        #pragma unroll
        for (int o = 16; o > 0; o >>= 1) {
            d0 += __shfl_xor_sync(0xffffffffu, d0, o);
            d1 += __shfl_xor_sync(0xffffffffu, d1, o);
            d2 += __shfl_xor_sync(0xffffffffu, d2, o);
            d3 += __shfl_xor_sync(0xffffffffu, d3, o);
        }

        online_update(d0, h0, m, s, acc);
        online_update(d1, h1, m, s, acc);
        online_update(d2, h2, m, s, acc);
        online_update(d3, h3, m, s, acc);
    }
    for (; i < n; ++i) {
        const float* p = base + (size_t)i * D;
        float4 h = *reinterpret_cast<const float4*>(p);
        float d = dot4(h, aj);
        #pragma unroll
        for (int o = 16; o > 0; o >>= 1)
            d += __shfl_xor_sync(0xffffffffu, d, o);
        online_update(d, h, m, s, acc);
    }

    // ---- Block combine in shared memory ----
    __shared__ float sm_m[WPB];
    __shared__ float sm_s[WPB];
    __shared__ __align__(16) float sm_acc[WPB][D];

    if (lane == 0) { sm_m[warp] = m; sm_s[warp] = s; }
    *reinterpret_cast<float4*>(&sm_acc[warp][lane * 4]) = acc;
    __syncthreads();

    if (threadIdx.x < D) {
        const int d = threadIdx.x;
        float M = -1e30f;
        #pragma unroll
        for (int w = 0; w < WPB; ++w) M = fmaxf(M, sm_m[w]);

        float st = 0.f, ad = 0.f;
        #pragma unroll
        for (int w = 0; w < WPB; ++w) {
            float c = __expf(sm_m[w] - M);
            st += sm_s[w] * c;
            ad += sm_acc[w][d] * c;
        }
        g_acc[blockIdx.x * D + d] = ad;
        if (d == 0) { g_m[blockIdx.x] = M; g_s[blockIdx.x] = st; }
    }
}

// ---- Pass 2: one 1024-thread block, fully parallel combine ----
__global__ __launch_bounds__(NT2)
void gat_pass2(float* __restrict__ out) {
    const int tid  = threadIdx.x;
    const int lane = tid & 31;
    const int warp = tid >> 5;

    __shared__ float sm_c[NB];       // exp(m_b - M)
    __shared__ float red[32];        // cross-warp reduce scratch
    __shared__ float sm_M, sm_S;
    __shared__ __align__(16) float sm_part[GRP][D];

    // --- Stage A: global max over g_m (296 parallel loads) ---
    float mv = (tid < NB) ? g_m[tid] : -1e30f;
    #pragma unroll
    for (int o = 16; o > 0; o >>= 1) mv = fmaxf(mv, __shfl_xor_sync(0xffffffffu, mv, o));
    if (lane == 0) red[warp] = mv;
    __syncthreads();
    if (warp == 0) {
        float v = red[lane];
        #pragma unroll
        for (int o = 16; o > 0; o >>= 1) v = fmaxf(v, __shfl_xor_sync(0xffffffffu, v, o));
        if (lane == 0) sm_M = v;
    }
    __syncthreads();
    const float M = sm_M;

    // --- Stage B: c_b = exp(m_b - M), S = sum(s_b * c_b) ---
    float sv = 0.f;
    if (tid < NB) {
        float c = __expf(g_m[tid] - M);
        sm_c[tid] = c;
        sv = g_s[tid] * c;
    }
    #pragma unroll
    for (int o = 16; o > 0; o >>= 1) sv += __shfl_xor_sync(0xffffffffu, sv, o);
    __syncthreads();                  // sm_c ready; re-use red[]
    if (lane == 0) red[warp] = sv;
    __syncthreads();
    if (warp == 0) {
        float v = red[lane];
        #pragma unroll
        for (int o = 16; o > 0; o >>= 1) v += __shfl_xor_sync(0xffffffffu, v, o);
        if (lane == 0) sm_S = v;
    }

    // --- Stage C: combine g_acc (296*128 floats) across all 1024 threads ---
    const int d   = tid & (D - 1);    // 0..127
    const int grp = tid >> 7;         // 0..7
    float ad = 0.f;
    for (int b = grp; b < NB; b += GRP)        // ~37 coalesced, independent loads
        ad += g_acc[b * D + d] * sm_c[b];
    sm_part[grp][d] = ad;
    __syncthreads();

    if (tid < D) {
        float total = 0.f;
        #pragma unroll
        for (int g = 0; g < GRP; ++g) total += sm_part[g][tid];
        float h = total / sm_S;
        out[tid] = (h > 0.f) ? h : expm1f(h);   // ELU, alpha = 1
    }
}

extern "C" void kernel_launch(void* const* d_in, const int* in_sizes, int n_in,
                              void* d_out, int out_size) {
    // inputs: [0] h_i (unused: constant logit shift cancels in softmax),
    //         [1] h_j [200000,128] f32, [2] a [256,1] f32
    const float* hj = (const float*)d_in[1];
    const float* a  = (const float*)d_in[2];
    const int nrows = in_sizes[1] / D;

    gat_pass1<<<NB, NT>>>(hj, a, nrows);
    gat_pass2<<<1, NT2>>>((float*)d_out);
}

// round 4
// speedup vs baseline: 1.7849x; 1.2493x over previous
#include <cuda_runtime.h>
#include <cuda_bf16.h>

// GraphAttentionLayer: out = elu(softmax(h_j @ a_j + const) @ h_j)
// Pass 1: single-pass online softmax over 200000x128 f32 (102.4 MB read once),
//         per-block partials (m, s, acc) written with acc TRANSPOSED (dim-major).
// h_i . a_i is a constant logit shift -> cancels in softmax -> skipped.
// Pass 2: 128 blocks (one per output dim), each combines 296 partials in parallel.

#define D        128
#define NB       296          // pass-1 blocks (2 * 148 SMs -> balanced 2-wave)
#define NT       512          // threads per block, pass 1
#define WPB      (NT / 32)    // 16 warps per block
#define NW       (NB * WPB)
#define NT2      256          // threads per block, pass 2

// Scratch (allocation-free rule -> __device__ globals)
__device__ float g_m[NB];
__device__ float g_s[NB];
__device__ float g_accT[D * NB];   // TRANSPOSED: [dim][block]

__device__ __forceinline__ float dot4(const float4& h, const float4& a) {
    return h.x * a.x + h.y * a.y + h.z * a.z + h.w * a.w;
}

__device__ __forceinline__ void online_update(float d, const float4& h,
                                              float& m, float& s, float4& acc) {
    float mn = fmaxf(m, d);
    float c  = __expf(m - mn);
    float w  = __expf(d - mn);
    s     = s * c + w;
    acc.x = acc.x * c + w * h.x;
    acc.y = acc.y * c + w * h.y;
    acc.z = acc.z * c + w * h.z;
    acc.w = acc.w * c + w * h.w;
    m = mn;
}

__global__ __launch_bounds__(NT)
void gat_pass1(const float* __restrict__ hj, const float* __restrict__ a, int nrows) {
    const int warp = threadIdx.x >> 5;
    const int lane = threadIdx.x & 31;

    const float4 aj = *reinterpret_cast<const float4*>(a + D + lane * 4);

    const int gw    = blockIdx.x * WPB + warp;
    const int chunk = (nrows + NW - 1) / NW;
    int r0 = gw * chunk;
    int r1 = r0 + chunk;
    if (r0 > nrows) r0 = nrows;
    if (r1 > nrows) r1 = nrows;
    const int n = (r1 > r0) ? (r1 - r0) : 0;

    float  m = -1e30f;
    float  s = 0.0f;
    float4 acc = make_float4(0.f, 0.f, 0.f, 0.f);

    const float* base = hj + (size_t)r0 * D + lane * 4;

    int i = 0;
    for (; i + 4 <= n; i += 4) {
        const float* p = base + (size_t)i * D;
        float4 h0 = *reinterpret_cast<const float4*>(p);
        float4 h1 = *reinterpret_cast<const float4*>(p + D);
        float4 h2 = *reinterpret_cast<const float4*>(p + 2 * D);
        float4 h3 = *reinterpret_cast<const float4*>(p + 3 * D);

        float d0 = dot4(h0, aj);
        float d1 = dot4(h1, aj);
        float d2 = dot4(h2, aj);
        float d3 = dot4(h3, aj);

        #pragma unroll
        for (int o = 16; o > 0; o >>= 1) {
            d0 += __shfl_xor_sync(0xffffffffu, d0, o);
            d1 += __shfl_xor_sync(0xffffffffu, d1, o);
            d2 += __shfl_xor_sync(0xffffffffu, d2, o);
            d3 += __shfl_xor_sync(0xffffffffu, d3, o);
        }

        online_update(d0, h0, m, s, acc);
        online_update(d1, h1, m, s, acc);
        online_update(d2, h2, m, s, acc);
        online_update(d3, h3, m, s, acc);
    }
    for (; i < n; ++i) {
        const float* p = base + (size_t)i * D;
        float4 h = *reinterpret_cast<const float4*>(p);
        float d = dot4(h, aj);
        #pragma unroll
        for (int o = 16; o > 0; o >>= 1)
            d += __shfl_xor_sync(0xffffffffu, d, o);
        online_update(d, h, m, s, acc);
    }

    // ---- Block combine in shared memory ----
    __shared__ float sm_m[WPB];
    __shared__ float sm_s[WPB];
    __shared__ __align__(16) float sm_acc[WPB][D];

    if (lane == 0) { sm_m[warp] = m; sm_s[warp] = s; }
    *reinterpret_cast<float4*>(&sm_acc[warp][lane * 4]) = acc;
    __syncthreads();

    if (threadIdx.x < D) {
        const int d = threadIdx.x;
        float M = -1e30f;
        #pragma unroll
        for (int w = 0; w < WPB; ++w) M = fmaxf(M, sm_m[w]);

        float st = 0.f, ad = 0.f;
        #pragma unroll
        for (int w = 0; w < WPB; ++w) {
            float c = __expf(sm_m[w] - M);
            st += sm_s[w] * c;
            ad += sm_acc[w][d] * c;
        }
        g_accT[d * NB + blockIdx.x] = ad;       // transposed write (dim-major)
        if (d == 0) { g_m[blockIdx.x] = M; g_s[blockIdx.x] = st; }
    }
}

// ---- Pass 2: one block per output dim; each block combines NB partials ----
__global__ __launch_bounds__(NT2)
void gat_pass2(float* __restrict__ out) {
    const int d    = blockIdx.x;      // 0..127
    const int t    = threadIdx.x;     // 0..255
    const int lane = t & 31;
    const int warp = t >> 5;

    __shared__ float red_m[NT2 / 32];
    __shared__ float red_s[NT2 / 32];
    __shared__ float red_a[NT2 / 32];
    __shared__ float sm_M;

    // Each thread owns partials t and t+256 (t+256 valid only for t < NB-256)
    const bool hi = (t + NT2) < NB;
    float m0 = g_m[t];
    float m1 = hi ? g_m[t + NT2] : -1e30f;

    // Block max over m
    float mv = fmaxf(m0, m1);
    #pragma unroll
    for (int o = 16; o > 0; o >>= 1) mv = fmaxf(mv, __shfl_xor_sync(0xffffffffu, mv, o));
    if (lane == 0) red_m[warp] = mv;
    __syncthreads();
    if (t == 0) {
        float v = red_m[0];
        #pragma unroll
        for (int w = 1; w < NT2 / 32; ++w) v = fmaxf(v, red_m[w]);
        sm_M = v;
    }
    __syncthreads();
    const float M = sm_M;

    // Weighted combine of s and acc (this dim's contiguous row of g_accT)
    const float* arow = g_accT + (size_t)d * NB;
    float c0 = __expf(m0 - M);
    float c1 = hi ? __expf(m1 - M) : 0.f;
    float sv = g_s[t] * c0 + (hi ? g_s[t + NT2] * c1 : 0.f);
    float av = arow[t] * c0 + (hi ? arow[t + NT2] * c1 : 0.f);

    #pragma unroll
    for (int o = 16; o > 0; o >>= 1) {
        sv += __shfl_xor_sync(0xffffffffu, sv, o);
        av += __shfl_xor_sync(0xffffffffu, av, o);
    }
    if (lane == 0) { red_s[warp] = sv; red_a[warp] = av; }
    __syncthreads();

    if (t == 0) {
        float S = 0.f, A = 0.f;
        #pragma unroll
        for (int w = 0; w < NT2 / 32; ++w) { S += red_s[w]; A += red_a[w]; }
        float h = A / S;
        out[d] = (h > 0.f) ? h : expm1f(h);    // ELU, alpha = 1
    }
}

extern "C" void kernel_launch(void* const* d_in, const int* in_sizes, int n_in,
                              void* d_out, int out_size) {
    // inputs: [0] h_i (unused: constant logit shift cancels in softmax),
    //         [1] h_j [200000,128] f32, [2] a [256,1] f32
    const float* hj = (const float*)d_in[1];
    const float* a  = (const float*)d_in[2];
    const int nrows = in_sizes[1] / D;

    gat_pass1<<<NB, NT>>>(hj, a, nrows);
    gat_pass2<<<D, NT2>>>((float*)d_out);
}